// round 9
// baseline (speedup 1.0000x reference)
#include <cuda_runtime.h>

// Problem dims (fixed)
#define BB   512
#define TT   100
#define II   700
#define HH   128
#define OO   20
#define NROWS (BB*TT)
#define MW   24                    // padded mask words per row (22 used + 2 zero)
#define CHUNK_I 192                // i-rows per gather chunk
#define CHUNK_W 6                  // mask words per chunk
#define TRANS_BLOCKS 350           // CTAs of fused kernel doing the transpose

#define ALPHA 0.81873075307798182f // exp(-0.2)
#define BETA  0.90483741803595957f // exp(-0.1)
#define LAM   0.95122942450071400f // exp(-0.05)

// Device-global scratch (allocation-free)
static __device__ float    g_W0T[II * HH];               // W0^T [i][h]
static __device__ unsigned g_masks[(size_t)NROWS * MW];  // input spike bitmasks (sequential)
static __device__ float    g_U[(size_t)NROWS * HH];      // U = X @ W0^T
static __device__ unsigned g_K0[(size_t)NROWS * 4];      // layer-0 spike masks
static __device__ float4   g_G4[(size_t)NROWS * 32];     // G interleaved: [row][lane] = {h=lane, +32, +64, +96}

// ---------------------------------------------------------------------------
// K0: FUSED transpose + input-bitmask extraction (MLP-6 loads).
// ---------------------------------------------------------------------------
__global__ void __launch_bounds__(256) k_fused_tm(const float* __restrict__ W0,
                                                  const float* __restrict__ X) {
    if (blockIdx.x < TRANS_BLOCKS) {
        int idx = blockIdx.x * 256 + threadIdx.x;   // covers II*HH = 89600 exactly
        int i = idx >> 7, h = idx & 127;
        g_W0T[idx] = W0[h * II + i];
        return;
    }
    int warp = ((blockIdx.x - TRANS_BLOCKS) * 256 + threadIdx.x) >> 5;
    int lane = threadIdx.x & 31;
    if (warp >= NROWS) return;
    const float4* xr4 = (const float4*)(X + (size_t)warp * II);

    // Issue all 6 loads up front (independent -> MLP 6)
    float4 v[6];
    #pragma unroll
    for (int k = 0; k < 6; k++) {
        v[k] = make_float4(0.f, 0.f, 0.f, 0.f);
        if (k < 5 || lane < 15)
            v[k] = __ldg(xr4 + k * 32 + lane);
    }

    unsigned mw = 0;
    int myk = lane >> 2;
    int myg = lane & 3;
    #pragma unroll
    for (int k = 0; k < 6; k++) {
        unsigned nib = (v[k].x != 0.f ? 1u : 0u) | (v[k].y != 0.f ? 2u : 0u)
                     | (v[k].z != 0.f ? 4u : 0u) | (v[k].w != 0.f ? 8u : 0u);
        unsigned part = nib << ((lane & 7) * 4);
        part |= __shfl_xor_sync(0xffffffffu, part, 1);
        part |= __shfl_xor_sync(0xffffffffu, part, 2);
        part |= __shfl_xor_sync(0xffffffffu, part, 4);
        unsigned wd = __shfl_sync(0xffffffffu, part, myg * 8);
        if (k == myk) mw = wd;
    }
    if (lane < MW) g_masks[(size_t)warp * MW + lane] = mw;
}

// ---------------------------------------------------------------------------
// K1..K4: U chunk passes (R6 measured geometry: 98 KB, 2 CTAs/SM, 296 CTAs).
// Running acc carried through g_U; additions ascending i -> bit-exact.
// ---------------------------------------------------------------------------
__global__ void __launch_bounds__(512, 2) k_gather(int chunk) {
    extern __shared__ float4 Ws4[];            // [192][32] float4
    const int w0 = chunk * CHUNK_W;

    for (int idx = threadIdx.x; idx < CHUNK_I * 32; idx += 512) {
        int i = idx >> 5, q = idx & 31;
        int gi = chunk * CHUNK_I + i;
        float4 v = make_float4(0.f, 0.f, 0.f, 0.f);
        if (gi < II) v = *(const float4*)(g_W0T + gi * HH + q * 4);
        Ws4[idx] = v;
    }
    __syncthreads();

    int warp = threadIdx.x >> 5, lane = threadIdx.x & 31;
    for (int row = blockIdx.x * 16 + warp; row < NROWS; row += gridDim.x * 16) {
        unsigned mw = (lane < CHUNK_W)
                    ? g_masks[(size_t)row * MW + w0 + lane] : 0u;
        float4* up = (float4*)(g_U + (size_t)row * HH) + lane;
        float4 acc;
        if (chunk == 0) acc = make_float4(0.f, 0.f, 0.f, 0.f);
        else            acc = *up;
        #pragma unroll
        for (int w = 0; w < CHUNK_W; w++) {
            unsigned m = __shfl_sync(0xffffffffu, mw, w);
            int base = w * 32;
            while (m) {
                int j = __ffs(m) - 1;
                m &= m - 1;
                float4 v = Ws4[(base + j) * 32 + lane];
                acc.x += v.x; acc.y += v.y; acc.z += v.z; acc.w += v.w;
            }
        }
        *up = acc;
    }
}

// ---------------------------------------------------------------------------
// K5: layer-0 LIF scan, prefetch depth 4.
// ---------------------------------------------------------------------------
__global__ void __launch_bounds__(256) k_layer0() {
    int w = blockIdx.x * 8 + (threadIdx.x >> 5);
    int lane = threadIdx.x & 31;
    int b = w >> 2, c = w & 3;
    if (b >= BB) return;

    const float* Ub = g_U + (size_t)b * TT * HH + c * 32 + lane;
    unsigned* K0b = g_K0 + (size_t)b * TT * 4 + c;

    float s0 = 0.f, m0 = 0.f;
    float buf[4];
    #pragma unroll
    for (int r = 0; r < 4; r++) buf[r] = Ub[(size_t)r * HH];

    for (int t0 = 0; t0 < TT; t0 += 4) {
        float nxt[4];
        #pragma unroll
        for (int r = 0; r < 4; r++) {
            int tn = t0 + 4 + r;
            nxt[r] = (tn < TT) ? Ub[(size_t)tn * HH] : 0.f;
        }
        #pragma unroll
        for (int r = 0; r < 4; r++) {
            s0 = ALPHA * s0 + buf[r];
            m0 = BETA * m0 + s0;
            bool sp = m0 > 1.0f;
            if (sp) m0 = 0.f;
            unsigned bm = __ballot_sync(0xffffffffu, sp);
            if (lane == 0) K0b[(size_t)(t0 + r) * 4] = bm;
        }
        #pragma unroll
        for (int r = 0; r < 4; r++) buf[r] = nxt[r];
    }
}

// ---------------------------------------------------------------------------
// K6: G = k0 @ W1^T, written INTERLEAVED: g_G4[row][lane] holds
// {h=lane, h=lane+32, h=lane+64, h=lane+96}. W1s4 in the same layout ->
// one LDS.128 per active j. Ascending-j adds per component -> bit-exact.
// ---------------------------------------------------------------------------
__global__ void __launch_bounds__(512, 2) k_gatherG(const float* __restrict__ W1) {
    extern __shared__ float4 W1s4[];           // [128 j][32 lane]
    for (int idx = threadIdx.x; idx < HH * 32; idx += 512) {
        int j = idx >> 5, ln = idx & 31;
        float4 v;
        v.x = W1[(ln      ) * HH + j];
        v.y = W1[(ln + 32 ) * HH + j];
        v.z = W1[(ln + 64 ) * HH + j];
        v.w = W1[(ln + 96 ) * HH + j];
        W1s4[idx] = v;
    }
    __syncthreads();

    int warp = threadIdx.x >> 5, lane = threadIdx.x & 31;
    for (int row = blockIdx.x * 16 + warp; row < NROWS; row += gridDim.x * 16) {
        unsigned mw = (lane < 4) ? g_K0[(size_t)row * 4 + lane] : 0u;
        float4 acc = make_float4(0.f, 0.f, 0.f, 0.f);
        #pragma unroll
        for (int q = 0; q < 4; q++) {
            unsigned m = __shfl_sync(0xffffffffu, mw, q);
            int base = q * 32;
            while (m) {
                int j = __ffs(m) - 1;
                m &= m - 1;
                float4 v = W1s4[(base + j) * 32 + lane];
                acc.x += v.x; acc.y += v.y; acc.z += v.z; acc.w += v.w;
            }
        }
        g_G4[(size_t)row * 32 + lane] = acc;
    }
}

// ---------------------------------------------------------------------------
// K7: layer-1 recurrence, WARP-PER-SAMPLE, zero barriers.
// Thread owns neurons {lane, lane+32, lane+64, lane+96}; spike masks are
// ballot results held in registers. V1s4 interleaved -> 1 LDS.128 per
// active j. k1 mask history -> SMEM (STS.128/step); readout + leaky scan
// post-loop (identical arithmetic order -> bit-exact).
// ---------------------------------------------------------------------------
__global__ void __launch_bounds__(128, 2) k_layer1(
    const float* __restrict__ V1, const float* __restrict__ Wr,
    const float* __restrict__ br, float* __restrict__ out)
{
    extern __shared__ float4 sm7[];
    float4* V1s4 = sm7;                             // [128][32] = 64 KB
    float*  Wrs  = (float*)(V1s4 + HH * 32);        // 128*20
    float*  brs  = Wrs + HH * OO;                   // 32
    uint4*  hist = (uint4*)(brs + 32);              // [4 warps][100]

    for (int idx = threadIdx.x; idx < HH * 32; idx += 128) {
        int j = idx >> 5, ln = idx & 31;
        float4 v;
        v.x = V1[(ln      ) * HH + j];
        v.y = V1[(ln + 32 ) * HH + j];
        v.z = V1[(ln + 64 ) * HH + j];
        v.w = V1[(ln + 96 ) * HH + j];
        V1s4[idx] = v;
    }
    for (int idx = threadIdx.x; idx < OO * HH; idx += 128) {
        int o = idx >> 7, j = idx & 127;
        Wrs[j * OO + o] = Wr[idx];
    }
    if (threadIdx.x < OO) brs[threadIdx.x] = br[threadIdx.x];
    __syncthreads();

    int warp = threadIdx.x >> 5, lane = threadIdx.x & 31;
    int b = blockIdx.x * 4 + warp;
    uint4* hw = hist + warp * TT;

    const float4* Gp = g_G4 + (size_t)b * TT * 32 + lane;
    float* outb = out + (size_t)b * TT * OO;

    float s1[4] = {0,0,0,0}, m1[4] = {0,0,0,0};
    unsigned p[4] = {0,0,0,0};
    float4 gv = __ldg(Gp);
    float4 g1 = __ldg(Gp + 32);

    for (int t = 0; t < TT; t++) {
        float4 g2 = (t + 2 < TT) ? __ldg(Gp + (size_t)(t + 2) * 32)
                                 : make_float4(0.f, 0.f, 0.f, 0.f);

        float a0 = 0.f, a1 = 0.f, a2 = 0.f, a3 = 0.f;
        #pragma unroll
        for (int q = 0; q < 4; q++) {
            unsigned m = p[q];
            int base = q * 32;
            while (m) {
                int j = __ffs(m) - 1;
                m &= m - 1;
                float4 v = V1s4[(base + j) * 32 + lane];
                a0 += v.x; a1 += v.y; a2 += v.z; a3 += v.w;
            }
        }

        float gvr[4] = {gv.x, gv.y, gv.z, gv.w};
        float ar[4]  = {a0, a1, a2, a3};
        #pragma unroll
        for (int r = 0; r < 4; r++) {
            s1[r] = (ALPHA * s1[r] + gvr[r]) + ar[r];
            m1[r] = BETA * m1[r] + s1[r];
            bool sp = m1[r] > 1.0f;
            if (sp) m1[r] = 0.f;
            p[r] = __ballot_sync(0xffffffffu, sp);
        }
        if (lane == 0) hw[t] = make_uint4(p[0], p[1], p[2], p[3]);
        gv = g1; g1 = g2;
    }
    __syncwarp();

    // Post-loop: lane o (<20) does readout gather + leaky scan for its channel.
    if (lane < OO) {
        const float C = 1.0f - LAM;
        float brv = brs[lane];
        float rp = 0.f;
        for (int t = 0; t < TT; t++) {
            uint4 ms = hw[t];
            float racc = brv;
            unsigned m;
            m = ms.x; while (m) { int j = __ffs(m) - 1; m &= m - 1; racc += Wrs[j * OO + lane]; }
            m = ms.y; while (m) { int j = __ffs(m) - 1; m &= m - 1; racc += Wrs[(32 + j) * OO + lane]; }
            m = ms.z; while (m) { int j = __ffs(m) - 1; m &= m - 1; racc += Wrs[(64 + j) * OO + lane]; }
            m = ms.w; while (m) { int j = __ffs(m) - 1; m &= m - 1; racc += Wrs[(96 + j) * OO + lane]; }
            rp = LAM * rp + C * racc;
            outb[(size_t)t * OO + lane] = rp;
        }
    }
}

// ---------------------------------------------------------------------------
// Launch
// ---------------------------------------------------------------------------
extern "C" void kernel_launch(void* const* d_in, const int* in_sizes, int n_in,
                              void* d_out, int out_size) {
    (void)in_sizes; (void)n_in; (void)out_size;
    const float* X  = (const float*)d_in[0];
    const float* W0 = (const float*)d_in[1];
    const float* W1 = (const float*)d_in[2];
    const float* V1 = (const float*)d_in[3];
    const float* Wr = (const float*)d_in[4];
    const float* br = (const float*)d_in[5];
    float* out = (float*)d_out;

    k_fused_tm<<<TRANS_BLOCKS + (NROWS + 7) / 8, 256>>>(W0, X);

    const size_t smem_g = (size_t)CHUNK_I * 32 * sizeof(float4);  // 98,304 B
    cudaFuncSetAttribute(k_gather, cudaFuncAttributeMaxDynamicSharedMemorySize,
                         (int)smem_g);
    for (int c = 0; c < 4; c++)
        k_gather<<<296, 512, smem_g>>>(c);

    k_layer0<<<256, 256>>>();

    const size_t smem_g1 = (size_t)HH * 32 * sizeof(float4);      // 64 KB
    cudaFuncSetAttribute(k_gatherG, cudaFuncAttributeMaxDynamicSharedMemorySize,
                         (int)smem_g1);
    k_gatherG<<<296, 512, smem_g1>>>(W1);

    const size_t smem_l1 = (size_t)HH * 32 * sizeof(float4)
                         + (size_t)(HH * OO + 32) * sizeof(float)
                         + (size_t)4 * TT * sizeof(uint4);        // ~81 KB
    cudaFuncSetAttribute(k_layer1, cudaFuncAttributeMaxDynamicSharedMemorySize,
                         (int)smem_l1);
    k_layer1<<<BB / 4, 128, smem_l1>>>(V1, Wr, br, out);
}

// round 10
// speedup vs baseline: 1.2990x; 1.2990x over previous
#include <cuda_runtime.h>

// Problem dims (fixed)
#define BB   512
#define TT   100
#define II   700
#define HH   128
#define OO   20
#define NROWS (BB*TT)
#define MW   24                    // padded mask words per row (22 used + 2 zero)
#define CHUNK_I 192                // i-rows per weight chunk
#define CHUNK_W 6                  // mask words per chunk
#define NCHUNK 4
#define GW_ROWS 11                 // rows per warp in single-pass gather
#define TRANS_BLOCKS 350           // CTAs of fused kernel doing the transpose

#define ALPHA 0.81873075307798182f // exp(-0.2)
#define BETA  0.90483741803595957f // exp(-0.1)
#define LAM   0.95122942450071400f // exp(-0.05)

// Device-global scratch (allocation-free)
static __device__ float    g_W0T[II * HH];               // W0^T [i][h]
static __device__ unsigned g_masks[(size_t)NROWS * MW];  // input spike bitmasks (sequential)
static __device__ float    g_U[(size_t)NROWS * HH];      // U = X @ W0^T
static __device__ unsigned g_K0[(size_t)NROWS * 4];      // layer-0 spike masks
static __device__ float    g_G[(size_t)NROWS * HH];      // G = k0 @ W1^T

// ---------------------------------------------------------------------------
// K0: FUSED transpose + input-bitmask extraction (MLP-6 loads, sequential
// bit order: word w bit j <-> element 32w+j, bit-exact with scalar encoding).
// ---------------------------------------------------------------------------
__global__ void __launch_bounds__(256) k_fused_tm(const float* __restrict__ W0,
                                                  const float* __restrict__ X) {
    if (blockIdx.x < TRANS_BLOCKS) {
        int idx = blockIdx.x * 256 + threadIdx.x;   // covers II*HH = 89600 exactly
        int i = idx >> 7, h = idx & 127;
        g_W0T[idx] = W0[h * II + i];
        return;
    }
    int warp = ((blockIdx.x - TRANS_BLOCKS) * 256 + threadIdx.x) >> 5;
    int lane = threadIdx.x & 31;
    if (warp >= NROWS) return;
    const float4* xr4 = (const float4*)(X + (size_t)warp * II);

    float4 v[6];
    #pragma unroll
    for (int k = 0; k < 6; k++) {
        v[k] = make_float4(0.f, 0.f, 0.f, 0.f);
        if (k < 5 || lane < 15)
            v[k] = __ldg(xr4 + k * 32 + lane);
    }

    unsigned mw = 0;
    int myk = lane >> 2;
    int myg = lane & 3;
    #pragma unroll
    for (int k = 0; k < 6; k++) {
        unsigned nib = (v[k].x != 0.f ? 1u : 0u) | (v[k].y != 0.f ? 2u : 0u)
                     | (v[k].z != 0.f ? 4u : 0u) | (v[k].w != 0.f ? 8u : 0u);
        unsigned part = nib << ((lane & 7) * 4);
        part |= __shfl_xor_sync(0xffffffffu, part, 1);
        part |= __shfl_xor_sync(0xffffffffu, part, 2);
        part |= __shfl_xor_sync(0xffffffffu, part, 4);
        unsigned wd = __shfl_sync(0xffffffffu, part, myg * 8);
        if (k == myk) mw = wd;
    }
    if (lane < MW) g_masks[(size_t)warp * MW + lane] = mw;
}

// ---------------------------------------------------------------------------
// K1: SINGLE-PASS U gather. Each warp owns 11 consecutive rows with full
// 128-float accumulators in registers (float4/lane x 11). The 4 weight
// chunks (192 rows x 128 h, 98 KB SMEM) are cycled internally with
// __syncthreads; masks preloaded once per row. Additions remain one-at-a-
// time ascending i -> bit-identical to a single ascending sweep. No g_U RMW.
// ---------------------------------------------------------------------------
__global__ void __launch_bounds__(256, 2) k_gather() {
    extern __shared__ float4 Ws4[];            // [192][32] float4
    int warp = threadIdx.x >> 5, lane = threadIdx.x & 31;
    int gw = blockIdx.x * 8 + warp;
    int r0 = gw * GW_ROWS;

    // Preload masks: lane L holds word L (<24) of each of this warp's rows.
    unsigned mw[GW_ROWS];
    #pragma unroll
    for (int k = 0; k < GW_ROWS; k++) {
        int row = r0 + k;
        mw[k] = (row < NROWS && lane < MW)
              ? g_masks[(size_t)row * MW + lane] : 0u;
    }

    float4 acc[GW_ROWS];
    #pragma unroll
    for (int k = 0; k < GW_ROWS; k++)
        acc[k] = make_float4(0.f, 0.f, 0.f, 0.f);

    for (int c = 0; c < NCHUNK; c++) {
        __syncthreads();
        for (int idx = threadIdx.x; idx < CHUNK_I * 32; idx += 256) {
            int i = idx >> 5, q = idx & 31;
            int gi = c * CHUNK_I + i;
            float4 v = make_float4(0.f, 0.f, 0.f, 0.f);
            if (gi < II) v = *(const float4*)(g_W0T + gi * HH + q * 4);
            Ws4[idx] = v;
        }
        __syncthreads();

        #pragma unroll
        for (int k = 0; k < GW_ROWS; k++) {
            #pragma unroll
            for (int w = 0; w < CHUNK_W; w++) {
                unsigned m = __shfl_sync(0xffffffffu, mw[k], c * CHUNK_W + w);
                int base = w * 32;
                while (m) {
                    int j = __ffs(m) - 1;
                    m &= m - 1;
                    float4 v = Ws4[(base + j) * 32 + lane];
                    acc[k].x += v.x; acc[k].y += v.y;
                    acc[k].z += v.z; acc[k].w += v.w;
                }
            }
        }
    }

    #pragma unroll
    for (int k = 0; k < GW_ROWS; k++) {
        int row = r0 + k;
        if (row < NROWS)
            ((float4*)(g_U + (size_t)row * HH))[lane] = acc[k];
    }
}

// ---------------------------------------------------------------------------
// K2: layer-0 LIF scan, prefetch depth 4.
// ---------------------------------------------------------------------------
__global__ void __launch_bounds__(256) k_layer0() {
    int w = blockIdx.x * 8 + (threadIdx.x >> 5);
    int lane = threadIdx.x & 31;
    int b = w >> 2, c = w & 3;
    if (b >= BB) return;

    const float* Ub = g_U + (size_t)b * TT * HH + c * 32 + lane;
    unsigned* K0b = g_K0 + (size_t)b * TT * 4 + c;

    float s0 = 0.f, m0 = 0.f;
    float buf[4];
    #pragma unroll
    for (int r = 0; r < 4; r++) buf[r] = Ub[(size_t)r * HH];

    for (int t0 = 0; t0 < TT; t0 += 4) {
        float nxt[4];
        #pragma unroll
        for (int r = 0; r < 4; r++) {
            int tn = t0 + 4 + r;
            nxt[r] = (tn < TT) ? Ub[(size_t)tn * HH] : 0.f;
        }
        #pragma unroll
        for (int r = 0; r < 4; r++) {
            s0 = ALPHA * s0 + buf[r];
            m0 = BETA * m0 + s0;
            bool sp = m0 > 1.0f;
            if (sp) m0 = 0.f;
            unsigned bm = __ballot_sync(0xffffffffu, sp);
            if (lane == 0) K0b[(size_t)(t0 + r) * 4] = bm;
        }
        #pragma unroll
        for (int r = 0; r < 4; r++) buf[r] = nxt[r];
    }
}

// ---------------------------------------------------------------------------
// K3: G[row] = sum over active j (k0, ascending) of W1T[j]. 64 KB SMEM,
// full-width float4, 2 CTAs/SM.
// ---------------------------------------------------------------------------
__global__ void __launch_bounds__(512, 2) k_gatherG(const float* __restrict__ W1) {
    extern __shared__ float W1s[];             // [128][128]
    for (int idx = threadIdx.x; idx < HH * HH; idx += 512) {
        int h = idx >> 7, j = idx & 127;
        W1s[j * 128 + h] = W1[idx];
    }
    __syncthreads();

    int warp = threadIdx.x >> 5, lane = threadIdx.x & 31;
    for (int row = blockIdx.x * 16 + warp; row < NROWS; row += gridDim.x * 16) {
        unsigned mw = (lane < 4) ? g_K0[(size_t)row * 4 + lane] : 0u;
        float4 acc = make_float4(0.f, 0.f, 0.f, 0.f);
        #pragma unroll
        for (int q = 0; q < 4; q++) {
            unsigned m = __shfl_sync(0xffffffffu, mw, q);
            int base = q * 32;
            while (m) {
                int j = __ffs(m) - 1;
                m &= m - 1;
                float4 v = *(const float4*)(W1s + (base + j) * 128 + lane * 4);
                acc.x += v.x; acc.y += v.y; acc.z += v.z; acc.w += v.w;
            }
        }
        *(float4*)(g_G + (size_t)row * HH + lane * 4) = acc;
    }
}

// ---------------------------------------------------------------------------
// K4: layer-1 recurrence, LEAN serial loop (R7 measured-good config).
// 2 samples/CTA (256 thr), 2 CTAs/SM = 16 warps/SM. Per-step: V-gather +
// LIF + ballot + barrier. k1 masks -> SMEM history; readout + leaky scan
// post-loop (identical arithmetic order -> bit-exact).
// ---------------------------------------------------------------------------
__global__ void __launch_bounds__(256, 2) k_layer1(
    const float* __restrict__ V1, const float* __restrict__ Wr,
    const float* __restrict__ br, float* __restrict__ out)
{
    extern __shared__ float sm6[];
    float* V1s = sm6;                               // 128*128      (64 KB)
    float* Wrs = V1s + HH * HH;                     // 128*20       (10 KB)
    float* brs = Wrs + HH * OO;                     // 32
    float* ybuf = brs + 32;                         // 2*100*20     (16 KB)
    unsigned* hist = (unsigned*)(ybuf + 2 * TT * OO); // 2*100*4    (3.2 KB)

    for (int idx = threadIdx.x; idx < HH * HH; idx += 256) {
        int h = idx >> 7, j = idx & 127;
        V1s[j * 128 + h] = V1[idx];
    }
    for (int idx = threadIdx.x; idx < OO * HH; idx += 256) {
        int o = idx >> 7, j = idx & 127;
        Wrs[j * OO + o] = Wr[idx];
    }
    if (threadIdx.x < OO) brs[threadIdx.x] = br[threadIdx.x];
    __syncthreads();

    int g    = threadIdx.x >> 7;     // sample in CTA
    int h    = threadIdx.x & 127;    // neuron
    int word = h >> 5;
    int lane = threadIdx.x & 31;
    int b    = blockIdx.x * 2 + g;
    unsigned* hg = hist + g * TT * 4;
    float* yg = ybuf + g * TT * OO;
    int barid = g + 1;

    const float* Gb = g_G + (size_t)b * TT * HH;
    float* outb = out + (size_t)b * TT * OO;

    float s1 = 0.f, m1 = 0.f;
    unsigned p0 = 0, p1 = 0, p2 = 0, p3 = 0;
    float gv = Gb[h];
    float g1 = Gb[HH + h];

    for (int t = 0; t < TT; t++) {
        float g2 = (t + 2 < TT) ? Gb[(size_t)(t + 2) * HH + h] : 0.f;

        float acc = 0.f;
        unsigned m;
        m = p0; while (m) { int j = __ffs(m) - 1; m &= m - 1; acc += V1s[j * 128 + h]; }
        m = p1; while (m) { int j = __ffs(m) - 1; m &= m - 1; acc += V1s[(32 + j) * 128 + h]; }
        m = p2; while (m) { int j = __ffs(m) - 1; m &= m - 1; acc += V1s[(64 + j) * 128 + h]; }
        m = p3; while (m) { int j = __ffs(m) - 1; m &= m - 1; acc += V1s[(96 + j) * 128 + h]; }

        s1 = (ALPHA * s1 + gv) + acc;
        m1 = BETA * m1 + s1;
        bool sp = m1 > 1.0f;
        if (sp) m1 = 0.f;

        unsigned bm = __ballot_sync(0xffffffffu, sp);
        if (lane == 0) hg[t * 4 + word] = bm;
        asm volatile("bar.sync %0, %1;" :: "r"(barid), "r"(128) : "memory");
        p0 = hg[t * 4 + 0]; p1 = hg[t * 4 + 1];
        p2 = hg[t * 4 + 2]; p3 = hg[t * 4 + 3];
        gv = g1; g1 = g2;
    }

    // Post-loop readout: 2000 (t,o) tasks over the group's 128 threads.
    for (int task = h; task < TT * OO; task += HH) {
        int t = task / OO, o = task - t * OO;
        float racc = brs[o];
        #pragma unroll
        for (int q = 0; q < 4; q++) {
            unsigned m = hg[t * 4 + q];
            int base = q * 32;
            while (m) {
                int j = __ffs(m) - 1;
                m &= m - 1;
                racc += Wrs[(base + j) * OO + o];
            }
        }
        yg[t * OO + o] = racc;
    }
    asm volatile("bar.sync %0, %1;" :: "r"(barid), "r"(128) : "memory");

    // Leaky scan per output channel (threads h < 20), identical rp chain.
    if (h < OO) {
        const float C = 1.0f - LAM;
        float rp = 0.f;
        for (int t = 0; t < TT; t++) {
            rp = LAM * rp + C * yg[t * OO + h];
            outb[(size_t)t * OO + h] = rp;
        }
    }
}

// ---------------------------------------------------------------------------
// Launch
// ---------------------------------------------------------------------------
extern "C" void kernel_launch(void* const* d_in, const int* in_sizes, int n_in,
                              void* d_out, int out_size) {
    (void)in_sizes; (void)n_in; (void)out_size;
    const float* X  = (const float*)d_in[0];
    const float* W0 = (const float*)d_in[1];
    const float* W1 = (const float*)d_in[2];
    const float* V1 = (const float*)d_in[3];
    const float* Wr = (const float*)d_in[4];
    const float* br = (const float*)d_in[5];
    float* out = (float*)d_out;

    k_fused_tm<<<TRANS_BLOCKS + (NROWS + 7) / 8, 256>>>(W0, X);

    const size_t smem_g = (size_t)CHUNK_I * 32 * sizeof(float4);  // 98,304 B
    cudaFuncSetAttribute(k_gather, cudaFuncAttributeMaxDynamicSharedMemorySize,
                         (int)smem_g);
    int n_gw = (NROWS + GW_ROWS - 1) / GW_ROWS;                   // 4655 warps
    k_gather<<<(n_gw + 7) / 8, 256, smem_g>>>();

    k_layer0<<<256, 256>>>();

    const size_t smem_g1 = (size_t)HH * HH * sizeof(float);       // 64 KB
    cudaFuncSetAttribute(k_gatherG, cudaFuncAttributeMaxDynamicSharedMemorySize,
                         (int)smem_g1);
    k_gatherG<<<296, 512, smem_g1>>>(W1);

    const size_t smem_l1 = (size_t)(HH * HH + HH * OO + 32 + 2 * TT * OO) * sizeof(float)
                         + 2 * TT * 4 * sizeof(unsigned);         // ~93 KB
    cudaFuncSetAttribute(k_layer1, cudaFuncAttributeMaxDynamicSharedMemorySize,
                         (int)smem_l1);
    k_layer1<<<BB / 2, 256, smem_l1>>>(V1, Wr, br, out);
}